// round 9
// baseline (speedup 1.0000x reference)
#include <cuda_runtime.h>
#include <cuda_bf16.h>

#define T_IN   4096
#define T2     8192
#define C_CH   512
#define B_N    16
#define THREADS 128
#define TOUT    8
#define SEGS   4
// staged x: raw [start-8, start+1031] = 1040 floats = 260 float4,
// padded +1 float4 per 8 -> 293 float4 slots
#define SXN4_PAD 293

// padded indexing: float4 idx -> idx + idx/8 ; float idx -> f + 4*(f/32)
#define PAD4(i)  ((i) + ((i) >> 3))
#define PADF(f)  ((f) + (((f) >> 5) << 2))

// kaiser_sinc_filter1d(0.25, 0.3, 12) — precomputed, symmetric (h[k]==h[11-k]).
#define H0 0.00202897f
#define H1 0.00938893f
#define H2 (-0.02554347f)
#define H3 (-0.05765742f)
#define H4 0.12857272f
#define H5 0.44321013f

// even u=2s:   y = sum_m UE[m]*x[s+m-3],  UE[m] = 2*h[11-2m]
// odd  u=2s+1: y = sum_m UO[m]*x[s+m-2],  UO[m] = 2*h[10-2m]
__device__ constexpr float UE[6] = { 2.0f*H0, 2.0f*H2, 2.0f*H4, 2.0f*H5, 2.0f*H3, 2.0f*H1 };
__device__ constexpr float UO[6] = { 2.0f*H1, 2.0f*H3, 2.0f*H5, 2.0f*H4, 2.0f*H2, 2.0f*H0 };
__device__ constexpr float DD[12] = { H0, H1, H2, H3, H4, H5, H5, H4, H3, H2, H1, H0 };

__global__ __launch_bounds__(THREADS)   // default reg target: 32 regs, full occupancy
void aa_act_kernel(const float* __restrict__ x,
                   const float* __restrict__ alpha,
                   const float* __restrict__ beta,
                   const float* __restrict__ uf,   // unused: taps are immediates
                   const float* __restrict__ df,   // unused
                   float* __restrict__ out)
{
    __shared__ __align__(16) float4 sx4[SXN4_PAD];
    float* sxf = reinterpret_cast<float*>(sx4);

    const int bx    = blockIdx.x;
    const int r     = bx >> 2;        // row = b*C + c
    const int seg   = bx & 3;
    const int start = seg << 10;
    const int c     = r & (C_CH - 1);
    const int tid   = threadIdx.x;
    const int base  = start - 8;      // raw x index of logical sx[0]

    const float* xrow = x + (size_t)r * T_IN;
    float* orow       = out + (size_t)r * T_IN;

    // ---- Vectorized staging into padded smem: logical sx[i] = x[clamp(base+i)] ----
    if (seg == 0) {
        const float4* s4p = reinterpret_cast<const float4*>(xrow);
#pragma unroll
        for (int it = 0; it < 3; ++it) {
            int i = tid + it * THREADS;
            if (i < 258) sx4[PAD4(i + 2)] = __ldg(s4p + i);
        }
        if (tid < 8) sxf[PADF(tid)] = __ldg(xrow);
    } else if (seg == 3) {
        const float4* s4p = reinterpret_cast<const float4*>(xrow + 3064);
#pragma unroll
        for (int it = 0; it < 3; ++it) {
            int i = tid + it * THREADS;
            if (i < 258) sx4[PAD4(i)] = __ldg(s4p + i);
        }
        if (tid < 8) sxf[PADF(1032 + tid)] = __ldg(xrow + (T_IN - 1));
    } else {
        const float4* s4p = reinterpret_cast<const float4*>(xrow + (start - 8));
#pragma unroll
        for (int it = 0; it < 3; ++it) {
            int i = tid + it * THREADS;
            if (i < 260) sx4[PAD4(i)] = __ldg(s4p + i);
        }
    }

    const float ea    = __expf(__ldg(alpha + c));
    const float ieb   = 1.0f / (__expf(__ldg(beta + c)) + 1e-9f);
    const float ea2   = 2.0f * ea;     // cos(2*ea*y)
    const float ieb2  = 0.5f * ieb;    // snake: y + ieb2 - ieb2*cos(2*ea*y)
    const float nieb2 = -ieb2;

    __syncthreads();

    const int t0 = start + tid * TOUT;
    const bool fast_ok = (t0 >= 3) && (t0 <= 4085);

    if (fast_ok) {
        float acc[TOUT];
#pragma unroll
        for (int q = 0; q < TOUT; q++) acc[q] = ieb2;   // folded snake constant

        // Split-window: first half uses x-floats 0..15 (4 LDS.128),
        // then 2 more LDS.128 for floats 16..23. Peak live ~16 x-floats.
        float rxA[16];
#pragma unroll
        for (int i = 0; i < 4; i++) {
            float4 v = sx4[PAD4(2 * tid + i)];
            rxA[4 * i + 0] = v.x; rxA[4 * i + 1] = v.y;
            rxA[4 * i + 2] = v.z; rxA[4 * i + 3] = v.w;
        }

        // y index u = 2*t0 - 5 + j, j=2i (odd u) / 2i+1 (even u)
        // i-loop half 1: i=0..6, window rxA[i+3 .. i+8] (max 14)
#pragma unroll
        for (int i = 0; i <= 6; ++i) {
            float yo = UO[0] * rxA[i + 3];
            float ye = UE[0] * rxA[i + 3];
#pragma unroll
            for (int m = 1; m < 6; ++m) {
                yo = fmaf(UO[m], rxA[i + 3 + m], yo);
                ye = fmaf(UE[m], rxA[i + 3 + m], ye);
            }
            float co = __cosf(yo * ea2);
            float ce = __cosf(ye * ea2);
            yo = fmaf(nieb2, co, yo);
            ye = fmaf(nieb2, ce, ye);
#pragma unroll
            for (int q = 0; q < TOUT; ++q) {
                const int k0 = 2 * i - 2 * q;
                if (k0 >= 0 && k0 < 12) acc[q] = fmaf(DD[k0], yo, acc[q]);
                const int k1 = 2 * i + 1 - 2 * q;
                if (k1 >= 0 && k1 < 12) acc[q] = fmaf(DD[k1], ye, acc[q]);
            }
        }

        float rxB[8];
#pragma unroll
        for (int i = 0; i < 2; i++) {
            float4 v = sx4[PAD4(2 * tid + 4 + i)];
            rxB[4 * i + 0] = v.x; rxB[4 * i + 1] = v.y;
            rxB[4 * i + 2] = v.z; rxB[4 * i + 3] = v.w;
        }

        // half 2: i=7..12, window floats i+3..i+8 (10..20): rxA[10..15] + rxB[0..4]
#pragma unroll
        for (int i = 7; i <= 12; ++i) {
            float yo, ye;
            {
                const int j0 = i + 3;
                float xv = (j0 < 16) ? rxA[j0] : rxB[j0 - 16];
                yo = UO[0] * xv;
                ye = UE[0] * xv;
            }
#pragma unroll
            for (int m = 1; m < 6; ++m) {
                const int j = i + 3 + m;
                float xv = (j < 16) ? rxA[j] : rxB[j - 16];
                yo = fmaf(UO[m], xv, yo);
                ye = fmaf(UE[m], xv, ye);
            }
            float co = __cosf(yo * ea2);
            float ce = __cosf(ye * ea2);
            yo = fmaf(nieb2, co, yo);
            ye = fmaf(nieb2, ce, ye);
#pragma unroll
            for (int q = 0; q < TOUT; ++q) {
                const int k0 = 2 * i - 2 * q;
                if (k0 >= 0 && k0 < 12) acc[q] = fmaf(DD[k0], yo, acc[q]);
                const int k1 = 2 * i + 1 - 2 * q;
                if (k1 >= 0 && k1 < 12) acc[q] = fmaf(DD[k1], ye, acc[q]);
            }
        }

        *reinterpret_cast<float4*>(orow + t0)     = make_float4(acc[0], acc[1], acc[2], acc[3]);
        *reinterpret_cast<float4*>(orow + t0 + 4) = make_float4(acc[4], acc[5], acc[6], acc[7]);
    } else {
        // Edge path (t0==0 or t0==4088): y-index clamping, padded scalar smem reads.
        float acc[TOUT];
#pragma unroll
        for (int q = 0; q < TOUT; q++) acc[q] = ieb2;

#pragma unroll 1
        for (int j = 0; j < 26; ++j) {
            int u = 2 * t0 - 5 + j;
            u = u < 0 ? 0 : (u > T2 - 1 ? T2 - 1 : u);
            const int s   = u >> 1;
            const int idx = s - base;
            float yv;
            if (u & 1) {
                yv = UO[0] * sxf[PADF(idx - 2)];
#pragma unroll
                for (int m = 1; m < 6; ++m) yv = fmaf(UO[m], sxf[PADF(idx + m - 2)], yv);
            } else {
                yv = UE[0] * sxf[PADF(idx - 3)];
#pragma unroll
                for (int m = 1; m < 6; ++m) yv = fmaf(UE[m], sxf[PADF(idx + m - 3)], yv);
            }
            float cc = __cosf(yv * ea2);
            yv = fmaf(nieb2, cc, yv);
#pragma unroll
            for (int q = 0; q < TOUT; ++q) {
                const int k = j - 2 * q;
                if (k >= 0 && k < 12) acc[q] = fmaf(DD[k], yv, acc[q]);
            }
        }
#pragma unroll
        for (int q = 0; q < TOUT; q++) orow[t0 + q] = acc[q];
    }
}

extern "C" void kernel_launch(void* const* d_in, const int* in_sizes, int n_in,
                              void* d_out, int out_size) {
    const float* x     = (const float*)d_in[0];
    const float* alpha = (const float*)d_in[1];
    const float* beta  = (const float*)d_in[2];
    const float* uf    = (const float*)d_in[3];
    const float* df    = (const float*)d_in[4];
    float* out = (float*)d_out;

    dim3 grid(B_N * C_CH * SEGS);   // 32768 blocks
    aa_act_kernel<<<grid, THREADS>>>(x, alpha, beta, uf, df, out);
}

// round 12
// speedup vs baseline: 1.4099x; 1.4099x over previous
#include <cuda_runtime.h>
#include <cuda_bf16.h>

#define T_IN   4096
#define T2     8192
#define C_CH   512
#define B_N    16
#define THREADS 128
#define TOUT    8
#define SEGS   4
// staged x: raw [start-8, start+1031] = 1040 floats = 260 float4s,
// de-interleaved: even float4s -> slots [0,130), odd float4s -> slots [0,130)
#define ODD_OFF 520   // floats (130 float4s * 4)

// kaiser_sinc_filter1d(0.25, 0.3, 12) — precomputed, symmetric (h[k]==h[11-k]).
#define H0 0.00202897f
#define H1 0.00938893f
#define H2 (-0.02554347f)
#define H3 (-0.05765742f)
#define H4 0.12857272f
#define H5 0.44321013f

// even u=2s:   y = sum_m UE[m]*x[s+m-3],  UE[m] = 2*h[11-2m]
// odd  u=2s+1: y = sum_m UO[m]*x[s+m-2],  UO[m] = 2*h[10-2m]
__device__ constexpr float UE[6] = { 2.0f*H0, 2.0f*H2, 2.0f*H4, 2.0f*H5, 2.0f*H3, 2.0f*H1 };
__device__ constexpr float UO[6] = { 2.0f*H1, 2.0f*H3, 2.0f*H5, 2.0f*H4, 2.0f*H2, 2.0f*H0 };
__device__ constexpr float DD[12] = { H0, H1, H2, H3, H4, H5, H5, H4, H3, H2, H1, H0 };

// scalar access into de-interleaved layout: logical float index f
__device__ __forceinline__ float sx_read(const float* s, int f) {
    return s[((f >> 2) & 1) * ODD_OFF + ((f >> 3) << 2) + (f & 3)];
}
__device__ __forceinline__ void sx_write(float* s, int f, float v) {
    s[((f >> 2) & 1) * ODD_OFF + ((f >> 3) << 2) + (f & 3)] = v;
}

__global__ __launch_bounds__(THREADS)
void aa_act_kernel(const float* __restrict__ x,
                   const float* __restrict__ alpha,
                   const float* __restrict__ beta,
                   const float* __restrict__ uf,   // unused: taps are immediates
                   const float* __restrict__ df,   // unused
                   float* __restrict__ out)
{
    __shared__ __align__(16) float sxf[2 * ODD_OFF];
    float4* ev4 = reinterpret_cast<float4*>(sxf);
    float4* od4 = reinterpret_cast<float4*>(sxf + ODD_OFF);

    const int bx    = blockIdx.x;
    const int r     = bx >> 2;        // row = b*C + c
    const int seg   = bx & 3;
    const int start = seg << 10;
    const int c     = r & (C_CH - 1);
    const int tid   = threadIdx.x;
    const int base  = start - 8;      // raw x index of logical sx[0]

    const float* xrow = x + (size_t)r * T_IN;
    float* orow       = out + (size_t)r * T_IN;

    // ---- Staging: logical sx[i] = x[clamp(base+i)], de-interleaved even/odd float4s.
    // Loop stride 128 => parity of logical float4 index is constant per thread.
    if (seg == 0) {
        // logical sx[0..7] = x[0] (left clamp); sx[8..1039] = x[0..1031]
        const float4* s4p = reinterpret_cast<const float4*>(xrow);
#pragma unroll
        for (int it = 0; it < 3; ++it) {
            int i = tid + it * THREADS;      // gmem float4 idx; logical idx = i+2
            if (i < 258) {
                float4 v = __ldg(s4p + i);
                int li = i + 2;
                if (li & 1) od4[li >> 1] = v; else ev4[li >> 1] = v;
            }
        }
        if (tid < 8) sx_write(sxf, tid, __ldg(xrow));
    } else if (seg == 3) {
        // sx[0..1031] = x[3064..4095]; sx[1032..1039] = x[4095] (right clamp)
        const float4* s4p = reinterpret_cast<const float4*>(xrow + 3064);
#pragma unroll
        for (int it = 0; it < 3; ++it) {
            int i = tid + it * THREADS;
            if (i < 258) {
                float4 v = __ldg(s4p + i);
                if (i & 1) od4[i >> 1] = v; else ev4[i >> 1] = v;
            }
        }
        if (tid < 8) sx_write(sxf, 1032 + tid, __ldg(xrow + (T_IN - 1)));
    } else {
        // fully interior: sx[0..1039] = x[start-8 .. start+1031]
        const float4* s4p = reinterpret_cast<const float4*>(xrow + (start - 8));
#pragma unroll
        for (int it = 0; it < 3; ++it) {
            int i = tid + it * THREADS;
            if (i < 260) {
                float4 v = __ldg(s4p + i);
                if (i & 1) od4[i >> 1] = v; else ev4[i >> 1] = v;
            }
        }
    }

    const float ea    = __expf(__ldg(alpha + c));
    const float ieb   = 1.0f / (__expf(__ldg(beta + c)) + 1e-9f);
    const float ea2   = 2.0f * ea;     // cos(2*ea*y)
    const float ieb2  = 0.5f * ieb;    // snake: y + ieb2 - ieb2*cos(2*ea*y)
    const float nieb2 = -ieb2;

    __syncthreads();

    const int t0 = start + tid * TOUT;
    const bool fast_ok = (t0 >= 3) && (t0 <= 4085);

    if (fast_ok) {
        // x window raw [t0-8, t0+15] -> rx[0..23]
        // logical float4s 2t..2t+5 = even slots t,t+1,t+2 + odd slots t,t+1,t+2
        // (16B lane stride -> conflict-free LDS.128)
        float rx[24];
        {
            float4 e0 = ev4[tid], o0 = od4[tid];
            float4 e1 = ev4[tid + 1], o1 = od4[tid + 1];
            float4 e2 = ev4[tid + 2], o2 = od4[tid + 2];
            rx[0]=e0.x;  rx[1]=e0.y;  rx[2]=e0.z;  rx[3]=e0.w;
            rx[4]=o0.x;  rx[5]=o0.y;  rx[6]=o0.z;  rx[7]=o0.w;
            rx[8]=e1.x;  rx[9]=e1.y;  rx[10]=e1.z; rx[11]=e1.w;
            rx[12]=o1.x; rx[13]=o1.y; rx[14]=o1.z; rx[15]=o1.w;
            rx[16]=e2.x; rx[17]=e2.y; rx[18]=e2.z; rx[19]=e2.w;
            rx[20]=o2.x; rx[21]=o2.y; rx[22]=o2.z; rx[23]=o2.w;
        }

        float acc[TOUT];
#pragma unroll
        for (int q = 0; q < TOUT; q++) acc[q] = ieb2;   // folded snake constant

        // y index u = 2*t0 - 5 + j, j=0..25; step i handles j=2i (u odd), j=2i+1 (u even)
#pragma unroll
        for (int i = 0; i < 13; ++i) {
            float yo = UO[0] * rx[i + 3];
            float ye = UE[0] * rx[i + 3];
#pragma unroll
            for (int m = 1; m < 6; ++m) {
                yo = fmaf(UO[m], rx[i + 3 + m], yo);
                ye = fmaf(UE[m], rx[i + 3 + m], ye);
            }
            // snake (3 ops): w = y - ieb2*cos(2*ea*y)   (+ieb2 folded into acc init)
            float co = __cosf(yo * ea2);
            float ce = __cosf(ye * ea2);
            yo = fmaf(nieb2, co, yo);
            ye = fmaf(nieb2, ce, ye);
            // scatter: y[j] feeds acc[q] with tap k = j - 2q in [0,12)
#pragma unroll
            for (int q = 0; q < TOUT; ++q) {
                const int k0 = 2 * i - 2 * q;       // yo (j = 2i)
                if (k0 >= 0 && k0 < 12) acc[q] = fmaf(DD[k0], yo, acc[q]);
                const int k1 = 2 * i + 1 - 2 * q;   // ye (j = 2i+1)
                if (k1 >= 0 && k1 < 12) acc[q] = fmaf(DD[k1], ye, acc[q]);
            }
        }

        *reinterpret_cast<float4*>(orow + t0)     = make_float4(acc[0], acc[1], acc[2], acc[3]);
        *reinterpret_cast<float4*>(orow + t0 + 4) = make_float4(acc[4], acc[5], acc[6], acc[7]);
    } else {
        // Edge path (t0==0 or t0==4088): y-index clamping, scalar de-interleaved reads.
        float acc[TOUT];
#pragma unroll
        for (int q = 0; q < TOUT; q++) acc[q] = ieb2;

#pragma unroll 1
        for (int j = 0; j < 26; ++j) {
            int u = 2 * t0 - 5 + j;
            u = u < 0 ? 0 : (u > T2 - 1 ? T2 - 1 : u);
            const int s   = u >> 1;
            const int idx = s - base;
            float yv;
            if (u & 1) {
                yv = UO[0] * sx_read(sxf, idx - 2);
#pragma unroll
                for (int m = 1; m < 6; ++m) yv = fmaf(UO[m], sx_read(sxf, idx + m - 2), yv);
            } else {
                yv = UE[0] * sx_read(sxf, idx - 3);
#pragma unroll
                for (int m = 1; m < 6; ++m) yv = fmaf(UE[m], sx_read(sxf, idx + m - 3), yv);
            }
            float cc = __cosf(yv * ea2);
            yv = fmaf(nieb2, cc, yv);
#pragma unroll
            for (int q = 0; q < TOUT; ++q) {
                const int k = j - 2 * q;
                if (k >= 0 && k < 12) acc[q] = fmaf(DD[k], yv, acc[q]);
            }
        }
#pragma unroll
        for (int q = 0; q < TOUT; q++) orow[t0 + q] = acc[q];
    }
}

extern "C" void kernel_launch(void* const* d_in, const int* in_sizes, int n_in,
                              void* d_out, int out_size) {
    const float* x     = (const float*)d_in[0];
    const float* alpha = (const float*)d_in[1];
    const float* beta  = (const float*)d_in[2];
    const float* uf    = (const float*)d_in[3];
    const float* df    = (const float*)d_in[4];
    float* out = (float*)d_out;

    dim3 grid(B_N * C_CH * SEGS);   // 32768 blocks
    aa_act_kernel<<<grid, THREADS>>>(x, alpha, beta, uf, df, out);
}

// round 13
// speedup vs baseline: 2.9414x; 2.0863x over previous
#include <cuda_runtime.h>
#include <cuda_bf16.h>

#define T_IN   4096
#define T2     8192
#define C_CH   512
#define B_N    16
#define THREADS 128
#define TOUT    8
#define NOUT_BLK 1024
#define SEGS   4
#define SXN    1048    // staged x: raw [start-12, start+1035], edge-clamped

// kaiser_sinc_filter1d(0.25, 0.3, 12) — precomputed, symmetric (h[k]==h[11-k]).
#define H0 0.00202897f
#define H1 0.00938893f
#define H2 (-0.02554347f)
#define H3 (-0.05765742f)
#define H4 0.12857272f
#define H5 0.44321013f

// Up-sampling polyphase taps (2x gain folded in):
// even u=2s:   y = sum_m UE[m]*x[s+m-3],  UE[m] = 2*h[11-2m]
// odd  u=2s+1: y = sum_m UO[m]*x[s+m-2],  UO[m] = 2*h[10-2m]
__device__ constexpr float UE[6] = { 2.0f*H0, 2.0f*H2, 2.0f*H4, 2.0f*H5, 2.0f*H3, 2.0f*H1 };
__device__ constexpr float UO[6] = { 2.0f*H1, 2.0f*H3, 2.0f*H5, 2.0f*H4, 2.0f*H2, 2.0f*H0 };
// Down-sampling taps
__device__ constexpr float DD[12] = { H0, H1, H2, H3, H4, H5, H5, H4, H3, H2, H1, H0 };

__global__ __launch_bounds__(THREADS)
void aa_act_kernel(const float* __restrict__ x,
                   const float* __restrict__ alpha,
                   const float* __restrict__ beta,
                   const float* __restrict__ uf,   // unused: taps are immediates
                   const float* __restrict__ df,   // unused
                   float* __restrict__ out)
{
    __shared__ __align__(16) float sx[SXN];

    const int bx    = blockIdx.x;
    const int r     = bx >> 2;        // row = b*C + c
    const int seg   = bx & 3;
    const int start = seg << 10;
    const int c     = r & (C_CH - 1);
    const int tid   = threadIdx.x;
    const int base  = start - 12;     // raw x index of sx[0]

    const float* xrow = x + (size_t)r * T_IN;
    float* orow       = out + (size_t)r * T_IN;

    // Stage x segment (+halo 12), edge-clamped.
#pragma unroll
    for (int it = 0; it < 9; ++it) {
        int i = tid + it * THREADS;
        if (i < SXN) {
            int gi = base + i;
            gi = gi < 0 ? 0 : (gi > T_IN - 1 ? T_IN - 1 : gi);
            sx[i] = __ldg(xrow + gi);
        }
    }

    const float ea    = __expf(__ldg(alpha + c));
    const float ieb   = 1.0f / (__expf(__ldg(beta + c)) + 1e-9f);
    const float ea2   = 2.0f * ea;     // snake uses cos(2*ea*y)
    const float ieb2  = 0.5f * ieb;    // snake: y + ieb2 - ieb2*cos(2*ea*y)
    const float nieb2 = -ieb2;

    __syncthreads();

    const int t0 = start + tid * TOUT;
    const bool fast_ok = (t0 >= 3) && (t0 <= 4085);

    if (fast_ok) {
        // x window: raw [t0-8, t0+15] -> rx[0..23]; local float4 index 2*tid+1 (16B aligned)
        float rx[24];
        const float4* s4 = reinterpret_cast<const float4*>(sx);
        const int q4 = 2 * tid + 1;
#pragma unroll
        for (int i = 0; i < 6; i++) {
            float4 v = s4[q4 + i];
            rx[4 * i + 0] = v.x; rx[4 * i + 1] = v.y;
            rx[4 * i + 2] = v.z; rx[4 * i + 3] = v.w;
        }

        float acc[8];
#pragma unroll
        for (int q = 0; q < 8; q++) acc[q] = ieb2;   // folded snake constant (taps sum to 1)

        // y index u = 2*t0 - 5 + j, j = 0..25.
        // j = 2i   -> u odd  : yo = sum_m UO[m]*rx[i+3+m]
        // j = 2i+1 -> u even : ye = sum_m UE[m]*rx[i+3+m]
#pragma unroll
        for (int i = 0; i < 13; ++i) {
            float yo = UO[0] * rx[i + 3];
            float ye = UE[0] * rx[i + 3];
#pragma unroll
            for (int m = 1; m < 6; ++m) {
                yo = fmaf(UO[m], rx[i + 3 + m], yo);
                ye = fmaf(UE[m], rx[i + 3 + m], ye);
            }
            // snake (3 ops): w = y - ieb2*cos(2*ea*y)   (+ieb2 folded into acc init)
            float co = __cosf(yo * ea2);
            float ce = __cosf(ye * ea2);
            yo = fmaf(nieb2, co, yo);
            ye = fmaf(nieb2, ce, ye);
            // scatter: y[j] feeds acc[q] with tap k = j - 2q, 0 <= k < 12
#pragma unroll
            for (int q = 0; q < 8; ++q) {
                const int k0 = 2 * i - 2 * q;       // for yo (j = 2i)
                if (k0 >= 0 && k0 < 12) acc[q] = fmaf(DD[k0], yo, acc[q]);
                const int k1 = 2 * i + 1 - 2 * q;   // for ye (j = 2i+1)
                if (k1 >= 0 && k1 < 12) acc[q] = fmaf(DD[k1], ye, acc[q]);
            }
        }

        *reinterpret_cast<float4*>(orow + t0)     = make_float4(acc[0], acc[1], acc[2], acc[3]);
        *reinterpret_cast<float4*>(orow + t0 + 4) = make_float4(acc[4], acc[5], acc[6], acc[7]);
    } else {
        // Edge path (t0==0 or t0==4088): same structure with y-index clamping.
        float acc[8];
#pragma unroll
        for (int q = 0; q < 8; q++) acc[q] = ieb2;

#pragma unroll
        for (int j = 0; j < 26; ++j) {
            int u = 2 * t0 - 5 + j;
            u = u < 0 ? 0 : (u > T2 - 1 ? T2 - 1 : u);
            const int s   = u >> 1;
            const int idx = s - base;          // sx index of x[s]
            float yv;
            if (u & 1) {
                yv = UO[0] * sx[idx - 2];
#pragma unroll
                for (int m = 1; m < 6; ++m) yv = fmaf(UO[m], sx[idx + m - 2], yv);
            } else {
                yv = UE[0] * sx[idx - 3];
#pragma unroll
                for (int m = 1; m < 6; ++m) yv = fmaf(UE[m], sx[idx + m - 3], yv);
            }
            float cc = __cosf(yv * ea2);
            yv = fmaf(nieb2, cc, yv);
#pragma unroll
            for (int q = 0; q < 8; ++q) {
                const int k = j - 2 * q;
                if (k >= 0 && k < 12) acc[q] = fmaf(DD[k], yv, acc[q]);
            }
        }
#pragma unroll
        for (int q = 0; q < 8; q++) orow[t0 + q] = acc[q];
    }
}

extern "C" void kernel_launch(void* const* d_in, const int* in_sizes, int n_in,
                              void* d_out, int out_size) {
    const float* x     = (const float*)d_in[0];
    const float* alpha = (const float*)d_in[1];
    const float* beta  = (const float*)d_in[2];
    const float* uf    = (const float*)d_in[3];
    const float* df    = (const float*)d_in[4];
    float* out = (float*)d_out;

    dim3 grid(B_N * C_CH * SEGS);   // 32768 blocks
    aa_act_kernel<<<grid, THREADS>>>(x, alpha, beta, uf, df, out);
}